// round 12
// baseline (speedup 1.0000x reference)
#include <cuda_runtime.h>
#include <cuda_fp16.h>
#include <cstdint>

#define B_   8
#define H_   16
#define NQ_  1024
#define NKV_ 2048
#define QSCALE 0.180336880f   /* 0.125 * log2(e) */

// fp16 scratch (no allocs allowed)
__device__ __align__(16) __half g_q[(size_t)B_*H_*NQ_*64];
__device__ __align__(16) __half g_k[(size_t)B_*H_*NKV_*64];
__device__ __align__(16) __half g_v[(size_t)B_*H_*NKV_*64];
__device__ __align__(16) __half g_o[(size_t)B_*NQ_*H_*64];
__device__ __align__(16) __half g_lat[(size_t)B_*NQ_*1024];
__device__ __align__(16) __half g_dat[(size_t)B_*NKV_*1024];
__device__ __align__(16) __half g_wq[1024*1024];
__device__ __align__(16) __half g_wk[1024*1024];
__device__ __align__(16) __half g_wv[1024*1024];
__device__ __align__(16) __half g_wo[1024*1024];

__device__ __forceinline__ uint32_t cvta_s(const void* p){ return (uint32_t)__cvta_generic_to_shared(p); }
__device__ __forceinline__ uint32_t packh2(float a, float b){
  __half2 h = __float22half2_rn(make_float2(a,b));
  return *reinterpret_cast<uint32_t*>(&h);
}
__device__ __forceinline__ void cpa16(uint32_t dst, const void* src){
  asm volatile("cp.async.cg.shared.global [%0],[%1],16;"::"r"(dst),"l"(src));
}
__device__ __forceinline__ void cp_commit(){ asm volatile("cp.async.commit_group;"); }
template<int N> __device__ __forceinline__ void cp_wait(){ asm volatile("cp.async.wait_group %0;"::"n"(N)); }
__device__ __forceinline__ void ldsm4(uint32_t* r, uint32_t a){
  asm volatile("ldmatrix.sync.aligned.m8n8.x4.shared.b16 {%0,%1,%2,%3},[%4];"
               :"=r"(r[0]),"=r"(r[1]),"=r"(r[2]),"=r"(r[3]):"r"(a));
}
__device__ __forceinline__ void ldsm4t(uint32_t* r, uint32_t a){
  asm volatile("ldmatrix.sync.aligned.m8n8.x4.trans.shared.b16 {%0,%1,%2,%3},[%4];"
               :"=r"(r[0]),"=r"(r[1]),"=r"(r[2]),"=r"(r[3]):"r"(a));
}
__device__ __forceinline__ void mma16816(float* c, const uint32_t* a, uint32_t b0, uint32_t b1){
  asm volatile("mma.sync.aligned.m16n8k16.row.col.f32.f16.f16.f32 "
               "{%0,%1,%2,%3},{%4,%5,%6,%7},{%8,%9},{%0,%1,%2,%3};"
               : "+f"(c[0]),"+f"(c[1]),"+f"(c[2]),"+f"(c[3])
               : "r"(a[0]),"r"(a[1]),"r"(a[2]),"r"(a[3]),"r"(b0),"r"(b1));
}

__device__ __forceinline__ void cvt8(const float* src, __half* dst, int i){
  const float4* s4 = (const float4*)src + (size_t)i*2;
  float4 a = s4[0], b = s4[1];
  uint4 v; v.x=packh2(a.x,a.y); v.y=packh2(a.z,a.w); v.z=packh2(b.x,b.y); v.w=packh2(b.z,b.w);
  ((uint4*)dst)[i] = v;
}

// ONE conversion launch
__global__ __launch_bounds__(256) void conv_all(const float* __restrict__ lat, const float* __restrict__ dat,
                                                const float* __restrict__ wq, const float* __restrict__ wk,
                                                const float* __restrict__ wv, const float* __restrict__ wo,
                                                __half* dlat, __half* ddat,
                                                __half* dwq, __half* dwk, __half* dwv, __half* dwo,
                                                int nLat8, int nDat8){
  int i = blockIdx.x*blockDim.x + threadIdx.x;
  if (i < nLat8){ cvt8(lat, dlat, i); return; }
  i -= nLat8;
  if (i < nDat8){ cvt8(dat, ddat, i); return; }
  i -= nDat8;
  const int sel = i >> 17, j = i & 131071;
  const float* s = (sel==0)? wq : (sel==1)? wk : (sel==2)? wv : wo;
  __half*      d = (sel==0)? dwq : (sel==1)? dwk : (sel==2)? dwv : dwo;
  cvt8(s, d, j);
}

// ---------------------------------------------------------------------------
// GEMM body: 256 threads, 8 warps (2m x 4n), warp tile 64x64, CTA 128x256,
// BK=64, 3-stage cp.async ring (48KB/stage = A16K + B32K), occ 1.
// Fragment double-buffering: kk+1 LDSMs issue ahead of kk's 32 indep HMMAs.
// ---------------------------------------------------------------------------
#define GSTAGE 49152

template<int MODE>
__device__ __forceinline__ void gemm_body(const __half* __restrict__ A,
                                          const __half* __restrict__ W,
                                          const float* __restrict__ bias,
                                          float* __restrict__ outF,
                                          __half* __restrict__ outH,
                                          int nrows, float scale, int m0, int n0,
                                          char* dsm)
{
  const int t = threadIdx.x, lane = t&31, w = t>>5, g = lane>>2, tq = lane&3;
  const int mw = (w>>2)*64, nw = (w&3)*64;
  const uint32_t sb = cvta_s(dsm);

  auto issue = [&](int kt, int st){
    const uint32_t ab = sb + st*GSTAGE, bb = ab + 16384;
    #pragma unroll
    for(int p=0;p<4;p++){                       // A: 128x64 = 1024 cpa16
      const int gid = p*256 + t, r = gid>>3, u = gid&7;
      cpa16(ab + (u*16 + (r>>3))*128 + (r&7)*16,
            A + (size_t)(m0+r)*1024 + kt*64 + u*8);
    }
    #pragma unroll
    for(int p=0;p<8;p++){                       // B: 64x256 = 2048 cpa16
      const int gid = p*256 + t, nb = gid&31, kr = gid>>5;
      cpa16(bb + (nb*8 + (kr>>3))*128 + (kr&7)*16,
            W + (size_t)(kt*64+kr)*1024 + n0 + nb*8);
    }
  };

  float acc[4][8][4];
  #pragma unroll
  for(int i=0;i<4;i++)
    #pragma unroll
    for(int j=0;j<8;j++){ acc[i][j][0]=0.f;acc[i][j][1]=0.f;acc[i][j][2]=0.f;acc[i][j][3]=0.f; }

  uint32_t af[2][4][4], bf[2][4][4];

  auto lfr = [&](int kk, int buf, uint32_t ab, uint32_t bb){
    #pragma unroll
    for(int ms=0;ms<4;ms++){
      const int rbm = ((mw+ms*16)>>3) + ((lane>>3)&1);
      ldsm4(af[buf][ms], ab + ((kk*2 + (lane>>4))*16 + rbm)*128 + (lane&7)*16);
    }
    #pragma unroll
    for(int j2=0;j2<4;j2++){
      const int nb = ((nw + j2*16)>>3) + (lane>>4);
      const int kb = kk*2 + ((lane>>3)&1);
      ldsm4t(bf[buf][j2], bb + (nb*8 + kb)*128 + (lane&7)*16);
    }
  };

  issue(0,0); cp_commit();
  issue(1,1); cp_commit();

  for(int kt=0; kt<16; kt++){
    if (kt<15) cp_wait<1>(); else cp_wait<0>();
    __syncthreads();
    if (kt+2<16){ issue(kt+2, (kt+2)%3); cp_commit(); }
    const int st = kt - (kt/3)*3;
    const uint32_t ab = sb + st*GSTAGE, bb = ab + 16384;
    lfr(0, 0, ab, bb);
    #pragma unroll
    for(int kk=0;kk<4;kk++){
      const int cur = kk&1, nxt = cur^1;
      if (kk<3) lfr(kk+1, nxt, ab, bb);
      #pragma unroll
      for(int ms=0;ms<4;ms++){
        #pragma unroll
        for(int j2=0;j2<4;j2++){
          mma16816(acc[ms][2*j2],   af[cur][ms], bf[cur][j2][0], bf[cur][j2][1]);
          mma16816(acc[ms][2*j2+1], af[cur][ms], bf[cur][j2][2], bf[cur][j2][3]);
        }
      }
    }
  }

  #pragma unroll
  for(int ms=0; ms<4; ms++){
    #pragma unroll
    for(int j=0;j<8;j++){
      const int col = n0 + nw + j*8 + 2*tq;
      const float b0v = bias[col], b1v = bias[col+1];
      const int r0 = m0 + mw + ms*16 + g;
      if (MODE==0){
        const int hh = col>>6, hd = col&63;
        int bb2 = r0/nrows, nn = r0 - bb2*nrows;
        size_t i0 = (((size_t)(bb2*H_+hh)*nrows + nn)<<6) + hd;
        *(__half2*)(outH + i0) =
          __float22half2_rn(make_float2((acc[ms][j][0]+b0v)*scale,(acc[ms][j][1]+b1v)*scale));
        const int r1 = r0+8;
        bb2 = r1/nrows; nn = r1 - bb2*nrows;
        size_t i1 = (((size_t)(bb2*H_+hh)*nrows + nn)<<6) + hd;
        *(__half2*)(outH + i1) =
          __float22half2_rn(make_float2((acc[ms][j][2]+b0v)*scale,(acc[ms][j][3]+b1v)*scale));
      } else {
        *(float2*)(outF + (size_t)r0*1024 + col) =
          make_float2(acc[ms][j][0]+b0v, acc[ms][j][1]+b1v);
        *(float2*)(outF + (size_t)(r0+8)*1024 + col) =
          make_float2(acc[ms][j][2]+b0v, acc[ms][j][3]+b1v);
      }
    }
  }
}

// Fused Q/K/V projections: grid (4, 320). y<64: Q, y<192: K, else V.
__global__ __launch_bounds__(256) void qkv_k(const __half* lat, const __half* dat,
                                             const __half* wq, const __half* wk, const __half* wv,
                                             const float* bq, const float* bk, const float* bv,
                                             __half* oq, __half* ok, __half* ov)
{
  extern __shared__ char dsm[];
  const int y = blockIdx.y;
  const __half *A, *W; const float* bias; __half* out; int nrows, m0; float sc;
  if (y < 64){       A=lat; W=wq; bias=bq; out=oq; nrows=NQ_;  m0=y*128;       sc=QSCALE; }
  else if (y < 192){ A=dat; W=wk; bias=bk; out=ok; nrows=NKV_; m0=(y-64)*128;  sc=1.0f; }
  else {             A=dat; W=wv; bias=bv; out=ov; nrows=NKV_; m0=(y-192)*128; sc=1.0f; }
  gemm_body<0>(A, W, bias, nullptr, out, nrows, sc, m0, blockIdx.x*256, dsm);
}

// Output projection: grid (4, 64)
__global__ __launch_bounds__(256) void gemmO_k(const __half* A, const __half* W,
                                               const float* bias, float* outF)
{
  extern __shared__ char dsm[];
  gemm_body<1>(A, W, bias, outF, nullptr, NQ_, 1.0f, blockIdx.y*128, blockIdx.x*256, dsm);
}

// ---------------------------------------------------------------------------
// Flash attention (unchanged): grid (8,16,8), 256 thr, KV chunk 32,
// 3-stage cp.async, occ 2. Q pre-scaled by 0.125*log2e; exp2f softmax.
// ---------------------------------------------------------------------------
__global__ __launch_bounds__(256,2) void attn_k()
{
  __shared__ __align__(16) __half Ks[3][32*64];
  __shared__ __align__(16) __half Vs[3][32*64];
  const int t = threadIdx.x, lane = t&31, w = t>>5, g = lane>>2, tq = lane&3;
  const int q0 = blockIdx.x*128, h = blockIdx.y, b = blockIdx.z;
  const uint32_t ksb = cvta_s(Ks), vsb = cvta_s(Vs);
  const __half* qg = g_q + ((size_t)(b*H_+h)*NQ_ + q0)*64;
  const __half* kg = g_k + (size_t)(b*H_+h)*NKV_*64;
  const __half* vg = g_v + (size_t)(b*H_+h)*NKV_*64;

  uint32_t qf[4][4];
  {
    const __half* qr0 = qg + (size_t)(w*16 + g)*64;
    const __half* qr1 = qr0 + 8*64;
    #pragma unroll
    for(int kk=0;kk<4;kk++){
      qf[kk][0] = *(const uint32_t*)(qr0 + kk*16 + tq*2);
      qf[kk][1] = *(const uint32_t*)(qr1 + kk*16 + tq*2);
      qf[kk][2] = *(const uint32_t*)(qr0 + kk*16 + 8 + tq*2);
      qf[kk][3] = *(const uint32_t*)(qr1 + kk*16 + 8 + tq*2);
    }
  }

  auto issue = [&](int c, int st){
    const int r = t&31, cb = (t>>5)&7;
    const uint32_t off = st*4096 + (cb*4 + (r>>3))*128 + (r&7)*16;
    const size_t gsrc = (size_t)(c*32 + r)*64 + cb*8;
    cpa16(ksb + off, kg + gsrc);
    cpa16(vsb + off, vg + gsrc);
  };

  float m0v=-1e30f, m1v=-1e30f, l0=0.f, l1=0.f;
  float o[8][4];
  #pragma unroll
  for(int j=0;j<8;j++){ o[j][0]=0.f;o[j][1]=0.f;o[j][2]=0.f;o[j][3]=0.f; }

  issue(0,0); cp_commit();
  issue(1,1); cp_commit();

  for(int c=0;c<64;c++){
    if (c<63) cp_wait<1>(); else cp_wait<0>();
    __syncthreads();
    if (c+2<64){ issue(c+2, (c+2)%3); cp_commit(); }
    const int st = c - (c/3)*3;
    const uint32_t kb0 = ksb + st*4096, vb0 = vsb + st*4096;

    float s[4][4];
    #pragma unroll
    for(int jt=0;jt<4;jt++){ s[jt][0]=0.f;s[jt][1]=0.f;s[jt][2]=0.f;s[jt][3]=0.f; }
    #pragma unroll
    for(int kk=0;kk<4;kk++){
      #pragma unroll
      for(int j2=0;j2<2;j2++){
        uint32_t bk[4];
        const int rb = j2*2 + (lane>>4);
        const int cb = kk*2 + ((lane>>3)&1);
        ldsm4(bk, kb0 + (cb*4 + rb)*128 + (lane&7)*16);
        mma16816(s[2*j2],   qf[kk], bk[0], bk[1]);
        mma16816(s[2*j2+1], qf[kk], bk[2], bk[3]);
      }
    }

    float mx0=-1e30f, mx1=-1e30f;
    #pragma unroll
    for(int jt=0;jt<4;jt++){
      mx0 = fmaxf(mx0, fmaxf(s[jt][0], s[jt][1]));
      mx1 = fmaxf(mx1, fmaxf(s[jt][2], s[jt][3]));
    }
    mx0 = fmaxf(mx0, __shfl_xor_sync(0xffffffffu, mx0, 1));
    mx0 = fmaxf(mx0, __shfl_xor_sync(0xffffffffu, mx0, 2));
    mx1 = fmaxf(mx1, __shfl_xor_sync(0xffffffffu, mx1, 1));
    mx1 = fmaxf(mx1, __shfl_xor_sync(0xffffffffu, mx1, 2));
    const float mn0 = fmaxf(m0v, mx0), mn1 = fmaxf(m1v, mx1);
    const float a0 = exp2f(m0v - mn0), a1 = exp2f(m1v - mn1);
    m0v = mn0; m1v = mn1;
    float r0s=0.f, r1s=0.f;
    #pragma unroll
    for(int jt=0;jt<4;jt++){
      s[jt][0] = exp2f(s[jt][0]-mn0); s[jt][1] = exp2f(s[jt][1]-mn0);
      s[jt][2] = exp2f(s[jt][2]-mn1); s[jt][3] = exp2f(s[jt][3]-mn1);
      r0s += s[jt][0]+s[jt][1]; r1s += s[jt][2]+s[jt][3];
    }
    l0 = a0*l0 + r0s; l1 = a1*l1 + r1s;
    #pragma unroll
    for(int j=0;j<8;j++){ o[j][0]*=a0; o[j][1]*=a0; o[j][2]*=a1; o[j][3]*=a1; }

    #pragma unroll
    for(int kt2=0;kt2<2;kt2++){
      uint32_t af[4];
      af[0] = packh2(s[2*kt2][0],   s[2*kt2][1]);
      af[1] = packh2(s[2*kt2][2],   s[2*kt2][3]);
      af[2] = packh2(s[2*kt2+1][0], s[2*kt2+1][1]);
      af[3] = packh2(s[2*kt2+1][2], s[2*kt2+1][3]);
      #pragma unroll
      for(int j2=0;j2<4;j2++){
        uint32_t bv[4];
        const int rb = kt2*2 + ((lane>>3)&1);
        const int cb = j2*2 + (lane>>4);
        ldsm4t(bv, vb0 + (cb*4 + rb)*128 + (lane&7)*16);
        mma16816(o[2*j2],   af, bv[0], bv[1]);
        mma16816(o[2*j2+1], af, bv[2], bv[3]);
      }
    }
  }

  l0 += __shfl_xor_sync(0xffffffffu, l0, 1);
  l0 += __shfl_xor_sync(0xffffffffu, l0, 2);
  l1 += __shfl_xor_sync(0xffffffffu, l1, 1);
  l1 += __shfl_xor_sync(0xffffffffu, l1, 2);
  const float i0 = 1.f/l0, i1 = 1.f/l1;
  const int row0 = q0 + w*16 + g;
  __half* og = g_o + (size_t)(b*NQ_)*1024 + (size_t)h*64;
  #pragma unroll
  for(int j=0;j<8;j++){
    const int col = j*8 + 2*tq;
    *(__half2*)(og + (size_t)row0*1024 + col) =
      __float22half2_rn(make_float2(o[j][0]*i0, o[j][1]*i0));
    *(__half2*)(og + (size_t)(row0+8)*1024 + col) =
      __float22half2_rn(make_float2(o[j][2]*i1, o[j][3]*i1));
  }
}

extern "C" void kernel_launch(void* const* d_in, const int* in_sizes, int n_in,
                              void* d_out, int out_size)
{
  const float* latent=(const float*)d_in[0];
  const float* data  =(const float*)d_in[1];
  const float* wq=(const float*)d_in[2]; const float* bq=(const float*)d_in[3];
  const float* wk=(const float*)d_in[4]; const float* bk=(const float*)d_in[5];
  const float* wv=(const float*)d_in[6]; const float* bv=(const float*)d_in[7];
  const float* wo=(const float*)d_in[8]; const float* bo=(const float*)d_in[9];

  __half *p_lat, *p_dat, *p_wq, *p_wk, *p_wv, *p_wo, *p_q, *p_k, *p_v, *p_o;
  cudaGetSymbolAddress((void**)&p_lat, g_lat);
  cudaGetSymbolAddress((void**)&p_dat, g_dat);
  cudaGetSymbolAddress((void**)&p_wq, g_wq);
  cudaGetSymbolAddress((void**)&p_wk, g_wk);
  cudaGetSymbolAddress((void**)&p_wv, g_wv);
  cudaGetSymbolAddress((void**)&p_wo, g_wo);
  cudaGetSymbolAddress((void**)&p_q, g_q);
  cudaGetSymbolAddress((void**)&p_k, g_k);
  cudaGetSymbolAddress((void**)&p_v, g_v);
  cudaGetSymbolAddress((void**)&p_o, g_o);

  const int dyn = 3*GSTAGE;   // 144KB
  cudaFuncSetAttribute(qkv_k,   cudaFuncAttributeMaxDynamicSharedMemorySize, dyn);
  cudaFuncSetAttribute(gemmO_k, cudaFuncAttributeMaxDynamicSharedMemorySize, dyn);

  const int nLat8 = B_*NQ_*1024/8, nDat8 = B_*NKV_*1024/8;
  const int nTot = nLat8 + nDat8 + 4*131072;
  conv_all<<<(nTot+255)/256, 256>>>(latent, data, wq, wk, wv, wo,
                                    p_lat, p_dat, p_wq, p_wk, p_wv, p_wo,
                                    nLat8, nDat8);

  qkv_k<<<dim3(4,320), 256, dyn>>>(p_lat, p_dat, p_wq, p_wk, p_wv,
                                   bq, bk, bv, p_q, p_k, p_v);
  attn_k<<<dim3(8,16,8), 256>>>();
  gemmO_k<<<dim3(4,64), 256, dyn>>>(p_o, p_wo, bo, (float*)d_out);
}

// round 13
// speedup vs baseline: 1.0654x; 1.0654x over previous
#include <cuda_runtime.h>
#include <cuda_fp16.h>
#include <cstdint>

#define B_   8
#define H_   16
#define NQ_  1024
#define NKV_ 2048
#define QSCALE 0.180336880f   /* 0.125 * log2(e) */

// fp16 scratch (no allocs allowed)
__device__ __align__(16) __half g_q[(size_t)B_*H_*NQ_*64];
__device__ __align__(16) __half g_k[(size_t)B_*H_*NKV_*64];
__device__ __align__(16) __half g_v[(size_t)B_*H_*NKV_*64];
__device__ __align__(16) __half g_o[(size_t)B_*NQ_*H_*64];
__device__ __align__(16) __half g_lat[(size_t)B_*NQ_*1024];
__device__ __align__(16) __half g_dat[(size_t)B_*NKV_*1024];
__device__ __align__(16) __half g_wq[1024*1024];
__device__ __align__(16) __half g_wk[1024*1024];
__device__ __align__(16) __half g_wv[1024*1024];
__device__ __align__(16) __half g_wo[1024*1024];

__device__ __forceinline__ uint32_t cvta_s(const void* p){ return (uint32_t)__cvta_generic_to_shared(p); }
__device__ __forceinline__ uint32_t packh2(float a, float b){
  __half2 h = __float22half2_rn(make_float2(a,b));
  return *reinterpret_cast<uint32_t*>(&h);
}
__device__ __forceinline__ void cpa16(uint32_t dst, const void* src){
  asm volatile("cp.async.cg.shared.global [%0],[%1],16;"::"r"(dst),"l"(src));
}
__device__ __forceinline__ void cp_commit(){ asm volatile("cp.async.commit_group;"); }
template<int N> __device__ __forceinline__ void cp_wait(){ asm volatile("cp.async.wait_group %0;"::"n"(N)); }
__device__ __forceinline__ void ldsm4(uint32_t* r, uint32_t a){
  asm volatile("ldmatrix.sync.aligned.m8n8.x4.shared.b16 {%0,%1,%2,%3},[%4];"
               :"=r"(r[0]),"=r"(r[1]),"=r"(r[2]),"=r"(r[3]):"r"(a));
}
__device__ __forceinline__ void ldsm4t(uint32_t* r, uint32_t a){
  asm volatile("ldmatrix.sync.aligned.m8n8.x4.trans.shared.b16 {%0,%1,%2,%3},[%4];"
               :"=r"(r[0]),"=r"(r[1]),"=r"(r[2]),"=r"(r[3]):"r"(a));
}
__device__ __forceinline__ void mma16816(float* c, const uint32_t* a, uint32_t b0, uint32_t b1){
  asm volatile("mma.sync.aligned.m16n8k16.row.col.f32.f16.f16.f32 "
               "{%0,%1,%2,%3},{%4,%5,%6,%7},{%8,%9},{%0,%1,%2,%3};"
               : "+f"(c[0]),"+f"(c[1]),"+f"(c[2]),"+f"(c[3])
               : "r"(a[0]),"r"(a[1]),"r"(a[2]),"r"(a[3]),"r"(b0),"r"(b1));
}

__device__ __forceinline__ void cvt8(const float* src, __half* dst, int i){
  const float4* s4 = (const float4*)src + (size_t)i*2;
  float4 a = s4[0], b = s4[1];
  uint4 v; v.x=packh2(a.x,a.y); v.y=packh2(a.z,a.w); v.z=packh2(b.x,b.y); v.w=packh2(b.z,b.w);
  ((uint4*)dst)[i] = v;
}

// ONE conversion launch
__global__ __launch_bounds__(256) void conv_all(const float* __restrict__ lat, const float* __restrict__ dat,
                                                const float* __restrict__ wq, const float* __restrict__ wk,
                                                const float* __restrict__ wv, const float* __restrict__ wo,
                                                __half* dlat, __half* ddat,
                                                __half* dwq, __half* dwk, __half* dwv, __half* dwo,
                                                int nLat8, int nDat8){
  int i = blockIdx.x*blockDim.x + threadIdx.x;
  if (i < nLat8){ cvt8(lat, dlat, i); return; }
  i -= nLat8;
  if (i < nDat8){ cvt8(dat, ddat, i); return; }
  i -= nDat8;
  const int sel = i >> 17, j = i & 131071;
  const float* s = (sel==0)? wq : (sel==1)? wk : (sel==2)? wv : wo;
  __half*      d = (sel==0)? dwq : (sel==1)? dwk : (sel==2)? dwv : dwo;
  cvt8(s, d, j);
}

// ---------------------------------------------------------------------------
// GEMM body: 256 threads, 8 warps (4m x 2n), warp tile 32x64, CTA 128x128,
// BK=32, SIX-stage cp.async ring (16KB/stage), occ 2. Prefetch depth 5:
// ~1000+ cycles of latency cover; only 4 cpa16 per thread per tile.
// ---------------------------------------------------------------------------
#define GSTAGE 16384
#define GDEPTH 6

template<int MODE>
__device__ __forceinline__ void gemm_body(const __half* __restrict__ A,
                                          const __half* __restrict__ W,
                                          const float* __restrict__ bias,
                                          float* __restrict__ outF,
                                          __half* __restrict__ outH,
                                          int nrows, float scale, int m0, int n0,
                                          char* dsm)
{
  const int t = threadIdx.x, lane = t&31, w = t>>5, g = lane>>2, tq = lane&3;
  const int mw = (w>>1)*32, nw = (w&1)*64;
  const uint32_t sb = cvta_s(dsm);

  auto issue = [&](int kt, int st){
    const uint32_t ab = sb + st*GSTAGE, bb = ab + 8192;
    #pragma unroll
    for(int p=0;p<2;p++){                      // A: 128x32 = 512 cpa16
      const int gid = p*256 + t, cb = gid>>7, r = gid&127;
      cpa16(ab + (cb*16 + (r>>3))*128 + (r&7)*16,
            A + (size_t)(m0+r)*1024 + kt*32 + cb*8);
    }
    #pragma unroll
    for(int p=0;p<2;p++){                      // B: 32x128 = 512 cpa16
      const int gid = p*256 + t, nb = gid&15, kr = gid>>4;
      cpa16(bb + (nb*4 + (kr>>3))*128 + (kr&7)*16,
            W + (size_t)(kt*32+kr)*1024 + n0 + nb*8);
    }
  };

  float acc[2][8][4];
  #pragma unroll
  for(int i=0;i<2;i++)
    #pragma unroll
    for(int j=0;j<8;j++){ acc[i][j][0]=0.f;acc[i][j][1]=0.f;acc[i][j][2]=0.f;acc[i][j][3]=0.f; }

  #pragma unroll
  for(int s=0;s<GDEPTH-1;s++){ issue(s, s); cp_commit(); }

  for(int kt=0; kt<32; kt++){
    cp_wait<GDEPTH-2>();          // tile kt resident (always GDEPTH-1 groups pending at top)
    __syncthreads();
    if (kt+GDEPTH-1 < 32) issue(kt+GDEPTH-1, (kt+GDEPTH-1)%GDEPTH);
    cp_commit();                  // empty group in tail keeps the count exact
    const int st = kt - (kt/GDEPTH)*GDEPTH;
    const uint32_t ab = sb + st*GSTAGE, bb = ab + 8192;
    #pragma unroll
    for(int kk=0;kk<2;kk++){
      uint32_t af[2][4];
      #pragma unroll
      for(int ms=0;ms<2;ms++){
        const int rbm = ((mw+ms*16)>>3) + ((lane>>3)&1);
        const int kbm = kk*2 + (lane>>4);
        ldsm4(af[ms], ab + (kbm*16 + rbm)*128 + (lane&7)*16);
      }
      #pragma unroll
      for(int j2=0;j2<4;j2++){
        uint32_t bf[4];
        const int kb = kk*2 + ((lane>>3)&1);
        const int nb = ((nw + j2*16)>>3) + (lane>>4);
        ldsm4t(bf, bb + (nb*4 + kb)*128 + (lane&7)*16);
        #pragma unroll
        for(int ms=0;ms<2;ms++){
          mma16816(acc[ms][2*j2],   af[ms], bf[0], bf[1]);
          mma16816(acc[ms][2*j2+1], af[ms], bf[2], bf[3]);
        }
      }
    }
  }

  #pragma unroll
  for(int ms=0; ms<2; ms++){
    #pragma unroll
    for(int j=0;j<8;j++){
      const int col = n0 + nw + j*8 + 2*tq;
      const float b0v = bias[col], b1v = bias[col+1];
      const int r0 = m0 + mw + ms*16 + g;
      if (MODE==0){
        const int hh = col>>6, hd = col&63;
        int bb2 = r0/nrows, nn = r0 - bb2*nrows;
        size_t i0 = (((size_t)(bb2*H_+hh)*nrows + nn)<<6) + hd;
        *(__half2*)(outH + i0) =
          __float22half2_rn(make_float2((acc[ms][j][0]+b0v)*scale,(acc[ms][j][1]+b1v)*scale));
        const int r1 = r0+8;
        bb2 = r1/nrows; nn = r1 - bb2*nrows;
        size_t i1 = (((size_t)(bb2*H_+hh)*nrows + nn)<<6) + hd;
        *(__half2*)(outH + i1) =
          __float22half2_rn(make_float2((acc[ms][j][2]+b0v)*scale,(acc[ms][j][3]+b1v)*scale));
      } else {
        *(float2*)(outF + (size_t)r0*1024 + col) =
          make_float2(acc[ms][j][0]+b0v, acc[ms][j][1]+b1v);
        *(float2*)(outF + (size_t)(r0+8)*1024 + col) =
          make_float2(acc[ms][j][2]+b0v, acc[ms][j][3]+b1v);
      }
    }
  }
}

// Fused Q/K/V projections: grid (8, 320). y<64: Q, y<192: K, else V.
__global__ __launch_bounds__(256,2) void qkv_k(const __half* lat, const __half* dat,
                                               const __half* wq, const __half* wk, const __half* wv,
                                               const float* bq, const float* bk, const float* bv,
                                               __half* oq, __half* ok, __half* ov)
{
  extern __shared__ char dsm[];
  const int y = blockIdx.y;
  const __half *A, *W; const float* bias; __half* out; int nrows, m0; float sc;
  if (y < 64){       A=lat; W=wq; bias=bq; out=oq; nrows=NQ_;  m0=y*128;       sc=QSCALE; }
  else if (y < 192){ A=dat; W=wk; bias=bk; out=ok; nrows=NKV_; m0=(y-64)*128;  sc=1.0f; }
  else {             A=dat; W=wv; bias=bv; out=ov; nrows=NKV_; m0=(y-192)*128; sc=1.0f; }
  gemm_body<0>(A, W, bias, nullptr, out, nrows, sc, m0, blockIdx.x*128, dsm);
}

// Output projection: grid (8, 64)
__global__ __launch_bounds__(256,2) void gemmO_k(const __half* A, const __half* W,
                                                 const float* bias, float* outF)
{
  extern __shared__ char dsm[];
  gemm_body<1>(A, W, bias, outF, nullptr, NQ_, 1.0f, blockIdx.y*128, blockIdx.x*128, dsm);
}

// ---------------------------------------------------------------------------
// Flash attention: grid (8,16,8), 256 thr, KV chunk 32, FOUR-stage cp.async
// ring (prefetch 3), occ 2. Q pre-scaled by 0.125*log2e; exp2f softmax.
// ---------------------------------------------------------------------------
__global__ __launch_bounds__(256,2) void attn_k()
{
  __shared__ __align__(16) __half Ks[4][32*64];
  __shared__ __align__(16) __half Vs[4][32*64];
  const int t = threadIdx.x, lane = t&31, w = t>>5, g = lane>>2, tq = lane&3;
  const int q0 = blockIdx.x*128, h = blockIdx.y, b = blockIdx.z;
  const uint32_t ksb = cvta_s(Ks), vsb = cvta_s(Vs);
  const __half* qg = g_q + ((size_t)(b*H_+h)*NQ_ + q0)*64;
  const __half* kg = g_k + (size_t)(b*H_+h)*NKV_*64;
  const __half* vg = g_v + (size_t)(b*H_+h)*NKV_*64;

  uint32_t qf[4][4];
  {
    const __half* qr0 = qg + (size_t)(w*16 + g)*64;
    const __half* qr1 = qr0 + 8*64;
    #pragma unroll
    for(int kk=0;kk<4;kk++){
      qf[kk][0] = *(const uint32_t*)(qr0 + kk*16 + tq*2);
      qf[kk][1] = *(const uint32_t*)(qr1 + kk*16 + tq*2);
      qf[kk][2] = *(const uint32_t*)(qr0 + kk*16 + 8 + tq*2);
      qf[kk][3] = *(const uint32_t*)(qr1 + kk*16 + 8 + tq*2);
    }
  }

  auto issue = [&](int c, int st){
    const int r = t&31, cb = (t>>5)&7;
    const uint32_t off = st*4096 + (cb*4 + (r>>3))*128 + (r&7)*16;
    const size_t gsrc = (size_t)(c*32 + r)*64 + cb*8;
    cpa16(ksb + off, kg + gsrc);
    cpa16(vsb + off, vg + gsrc);
  };

  float m0v=-1e30f, m1v=-1e30f, l0=0.f, l1=0.f;
  float o[8][4];
  #pragma unroll
  for(int j=0;j<8;j++){ o[j][0]=0.f;o[j][1]=0.f;o[j][2]=0.f;o[j][3]=0.f; }

  issue(0,0); cp_commit();
  issue(1,1); cp_commit();
  issue(2,2); cp_commit();

  for(int c=0;c<64;c++){
    cp_wait<2>();              // chunk c resident (3 groups pending at top)
    __syncthreads();
    if (c+3<64) issue(c+3, (c+3)&3);
    cp_commit();               // empty group in tail keeps the count exact
    const int st = c&3;
    const uint32_t kb0 = ksb + st*4096, vb0 = vsb + st*4096;

    float s[4][4];
    #pragma unroll
    for(int jt=0;jt<4;jt++){ s[jt][0]=0.f;s[jt][1]=0.f;s[jt][2]=0.f;s[jt][3]=0.f; }
    #pragma unroll
    for(int kk=0;kk<4;kk++){
      #pragma unroll
      for(int j2=0;j2<2;j2++){
        uint32_t bk[4];
        const int rb = j2*2 + (lane>>4);
        const int cb = kk*2 + ((lane>>3)&1);
        ldsm4(bk, kb0 + (cb*4 + rb)*128 + (lane&7)*16);
        mma16816(s[2*j2],   qf[kk], bk[0], bk[1]);
        mma16816(s[2*j2+1], qf[kk], bk[2], bk[3]);
      }
    }

    float mx0=-1e30f, mx1=-1e30f;
    #pragma unroll
    for(int jt=0;jt<4;jt++){
      mx0 = fmaxf(mx0, fmaxf(s[jt][0], s[jt][1]));
      mx1 = fmaxf(mx1, fmaxf(s[jt][2], s[jt][3]));
    }
    mx0 = fmaxf(mx0, __shfl_xor_sync(0xffffffffu, mx0, 1));
    mx0 = fmaxf(mx0, __shfl_xor_sync(0xffffffffu, mx0, 2));
    mx1 = fmaxf(mx1, __shfl_xor_sync(0xffffffffu, mx1, 1));
    mx1 = fmaxf(mx1, __shfl_xor_sync(0xffffffffu, mx1, 2));
    const float mn0 = fmaxf(m0v, mx0), mn1 = fmaxf(m1v, mx1);
    const float a0 = exp2f(m0v - mn0), a1 = exp2f(m1v - mn1);
    m0v = mn0; m1v = mn1;
    float r0s=0.f, r1s=0.f;
    #pragma unroll
    for(int jt=0;jt<4;jt++){
      s[jt][0] = exp2f(s[jt][0]-mn0); s[jt][1] = exp2f(s[jt][1]-mn0);
      s[jt][2] = exp2f(s[jt][2]-mn1); s[jt][3] = exp2f(s[jt][3]-mn1);
      r0s += s[jt][0]+s[jt][1]; r1s += s[jt][2]+s[jt][3];
    }
    l0 = a0*l0 + r0s; l1 = a1*l1 + r1s;
    #pragma unroll
    for(int j=0;j<8;j++){ o[j][0]*=a0; o[j][1]*=a0; o[j][2]*=a1; o[j][3]*=a1; }

    #pragma unroll
    for(int kt2=0;kt2<2;kt2++){
      uint32_t af[4];
      af[0] = packh2(s[2*kt2][0],   s[2*kt2][1]);
      af[1] = packh2(s[2*kt2][2],   s[2*kt2][3]);
      af[2] = packh2(s[2*kt2+1][0], s[2*kt2+1][1]);
      af[3] = packh2(s[2*kt2+1][2], s[2*kt2+1][3]);
      #pragma unroll
      for(int j2=0;j2<4;j2++){
        uint32_t bv[4];
        const int rb = kt2*2 + ((lane>>3)&1);
        const int cb = j2*2 + (lane>>4);
        ldsm4t(bv, vb0 + (cb*4 + rb)*128 + (lane&7)*16);
        mma16816(o[2*j2],   af, bv[0], bv[1]);
        mma16816(o[2*j2+1], af, bv[2], bv[3]);
      }
    }
  }

  l0 += __shfl_xor_sync(0xffffffffu, l0, 1);
  l0 += __shfl_xor_sync(0xffffffffu, l0, 2);
  l1 += __shfl_xor_sync(0xffffffffu, l1, 1);
  l1 += __shfl_xor_sync(0xffffffffu, l1, 2);
  const float i0 = 1.f/l0, i1 = 1.f/l1;
  const int row0 = q0 + w*16 + g;
  __half* og = g_o + (size_t)(b*NQ_)*1024 + (size_t)h*64;
  #pragma unroll
  for(int j=0;j<8;j++){
    const int col = j*8 + 2*tq;
    *(__half2*)(og + (size_t)row0*1024 + col) =
      __float22half2_rn(make_float2(o[j][0]*i0, o[j][1]*i0));
    *(__half2*)(og + (size_t)(row0+8)*1024 + col) =
      __float22half2_rn(make_float2(o[j][2]*i1, o[j][3]*i1));
  }
}

extern "C" void kernel_launch(void* const* d_in, const int* in_sizes, int n_in,
                              void* d_out, int out_size)
{
  const float* latent=(const float*)d_in[0];
  const float* data  =(const float*)d_in[1];
  const float* wq=(const float*)d_in[2]; const float* bq=(const float*)d_in[3];
  const float* wk=(const float*)d_in[4]; const float* bk=(const float*)d_in[5];
  const float* wv=(const float*)d_in[6]; const float* bv=(const float*)d_in[7];
  const float* wo=(const float*)d_in[8]; const float* bo=(const float*)d_in[9];

  __half *p_lat, *p_dat, *p_wq, *p_wk, *p_wv, *p_wo, *p_q, *p_k, *p_v, *p_o;
  cudaGetSymbolAddress((void**)&p_lat, g_lat);
  cudaGetSymbolAddress((void**)&p_dat, g_dat);
  cudaGetSymbolAddress((void**)&p_wq, g_wq);
  cudaGetSymbolAddress((void**)&p_wk, g_wk);
  cudaGetSymbolAddress((void**)&p_wv, g_wv);
  cudaGetSymbolAddress((void**)&p_wo, g_wo);
  cudaGetSymbolAddress((void**)&p_q, g_q);
  cudaGetSymbolAddress((void**)&p_k, g_k);
  cudaGetSymbolAddress((void**)&p_v, g_v);
  cudaGetSymbolAddress((void**)&p_o, g_o);

  const int dyn = GDEPTH*GSTAGE;   // 96KB
  cudaFuncSetAttribute(qkv_k,   cudaFuncAttributeMaxDynamicSharedMemorySize, dyn);
  cudaFuncSetAttribute(gemmO_k, cudaFuncAttributeMaxDynamicSharedMemorySize, dyn);

  const int nLat8 = B_*NQ_*1024/8, nDat8 = B_*NKV_*1024/8;
  const int nTot = nLat8 + nDat8 + 4*131072;
  conv_all<<<(nTot+255)/256, 256>>>(latent, data, wq, wk, wv, wo,
                                    p_lat, p_dat, p_wq, p_wk, p_wv, p_wo,
                                    nLat8, nDat8);

  qkv_k<<<dim3(8,320), 256, dyn>>>(p_lat, p_dat, p_wq, p_wk, p_wv,
                                   bq, bk, bv, p_q, p_k, p_v);
  attn_k<<<dim3(8,16,8), 256>>>();
  gemmO_k<<<dim3(8,64), 256, dyn>>>(p_o, p_wo, bo, (float*)d_out);
}